// round 14
// baseline (speedup 1.0000x reference)
#include <cuda_runtime.h>
#include <cuda_bf16.h>
#include <math.h>

#define NB 8
#define NC 256
#define HWF 4096
#define HW4 1024
#define EPSV 1e-5f
#define LOG2E 1.4426950408889634f

// ---------------- scratch (static __device__, word-typed, no allocation) ----
__device__ unsigned g_wpb [24576];               // proj wT bf16 [k=256][m=192], alpha-folded (m-pairs/word)
__device__ float    g_abp[2 * 192];              // proj beta
__device__ unsigned g_fb [NB * 32 * 512];        // f bf16 [b][k=32][n=1024]  (log2e folded)
__device__ unsigned g_gb [NB * 32 * 2048];       // g bf16 [b][k=32][m=4096]
__device__ unsigned g_hh2[NB * 1024 * 64];       // hh bf16 [b][n=1024][c=128]

// ---------------- helpers ----------------
__device__ __forceinline__ unsigned packbf(float a, float b) {
    __nv_bfloat162 t = __floats2bfloat162_rn(a, b);
    return *(unsigned*)&t;
}
__device__ __forceinline__ float ex2f(float f) {
    float r; asm("ex2.approx.ftz.f32 %0, %1;" : "=f"(r) : "f"(f)); return r;
}
__device__ __forceinline__ void cpa16(void* s, const void* g) {
    unsigned a = (unsigned)__cvta_generic_to_shared(s);
    asm volatile("cp.async.ca.shared.global [%0], [%1], 16;" :: "r"(a), "l"(g));
}
__device__ __forceinline__ void cp_commit() { asm volatile("cp.async.commit_group;"); }
template<int N> __device__ __forceinline__ void cp_wait() {
    asm volatile("cp.async.wait_group %0;" :: "n"(N));
}
__device__ __forceinline__ void ldsm4t(unsigned* r, const __nv_bfloat16* p) {
    unsigned a = (unsigned)__cvta_generic_to_shared(p);
    asm volatile("ldmatrix.sync.aligned.m8n8.x4.trans.shared.b16 {%0,%1,%2,%3}, [%4];"
                 : "=r"(r[0]), "=r"(r[1]), "=r"(r[2]), "=r"(r[3]) : "r"(a));
}
__device__ __forceinline__ void mma16(float* d, const unsigned* a, const unsigned* b) {
    asm volatile(
        "mma.sync.aligned.m16n8k16.row.col.f32.bf16.bf16.f32 "
        "{%0,%1,%2,%3},{%4,%5,%6,%7},{%8,%9},{%0,%1,%2,%3};"
        : "+f"(d[0]), "+f"(d[1]), "+f"(d[2]), "+f"(d[3])
        : "r"(a[0]), "r"(a[1]), "r"(a[2]), "r"(a[3]), "r"(b[0]), "r"(b[1]));
}

// A-frag (m16k16) from [k][row] smem, stride S halfwords, via ldmatrix.x4.trans
template<int S>
__device__ __forceinline__ void lda(unsigned* a, const __nv_bfloat16* base,
                                    int mo, int k0, int lane) {
    int grp = lane >> 3, j = lane & 7;
    int row = k0 + ((grp & 2) << 2) + j;
    int col = mo + ((grp & 1) << 3);
    ldsm4t(a, base + row * S + col);
}
// two B-frags (n8k16 at no, no+8) in one x4.trans
template<int S>
__device__ __forceinline__ void ldb2(unsigned* b, const __nv_bfloat16* base,
                                     int no, int k0, int lane) {
    int grp = lane >> 3, j = lane & 7;
    int row = k0 + ((grp & 1) << 3) + j;
    int col = no + ((grp >> 1) << 3);
    ldsm4t(b, base + row * S + col);
}

// one 32-deep k tile. As[k][m] stride AS, Bs[k][n] stride BS (halfwords).
template<int MF, int NF, int AS, int BS>
__device__ __forceinline__ void mma_ktile(const __nv_bfloat16* As, const __nv_bfloat16* Bs,
                                          int mBase, int nBase, int lane,
                                          float (*acc)[NF][4])
{
#pragma unroll
    for (int ks = 0; ks < 2; ks++) {
        unsigned a[MF][4], b[NF][2];
#pragma unroll
        for (int i = 0; i < MF; i++) lda<AS>(a[i], As, mBase + i * 16, ks * 16, lane);
#pragma unroll
        for (int j = 0; j < NF; j += 2) {
            unsigned bb[4];
            ldb2<BS>(bb, Bs, nBase + j * 8, ks * 16, lane);
            b[j][0] = bb[0]; b[j][1] = bb[1];
            b[j + 1][0] = bb[2]; b[j + 1][1] = bb[3];
        }
#pragma unroll
        for (int i = 0; i < MF; i++)
#pragma unroll
            for (int j = 0; j < NF; j++)
                mma16(acc[i][j], a[i], b[j]);
    }
}

// =====================================================================
// pre: proj weights only, coalesced along k. grid 25 x 256.
// =====================================================================
__global__ void pre_kernel(const float* __restrict__ w1, const float* __restrict__ w2,
                           const float* __restrict__ w3,
                           const float* __restrict__ b1, const float* __restrict__ s1,
                           const float* __restrict__ t1, const float* __restrict__ m1,
                           const float* __restrict__ v1,
                           const float* __restrict__ b2, const float* __restrict__ s2,
                           const float* __restrict__ t2, const float* __restrict__ m2,
                           const float* __restrict__ v2,
                           const float* __restrict__ b3, const float* __restrict__ s3,
                           const float* __restrict__ t3, const float* __restrict__ m3,
                           const float* __restrict__ v3)
{
    int idx = blockIdx.x * 256 + threadIdx.x;
    if (idx < 6144) {                        // wpb: mw (m-pair) x kc (k-chunk of 4)
        int mw = idx >> 6, kc = idx & 63;
        int m = 2 * mw;
        const float *r0, *r1;
        float a0, a1;
        if (m < 32)      { r0 = w1 + m * 256;        r1 = r0 + 256;
                           a0 = s1[m] * rsqrtf(v1[m] + EPSV) * LOG2E;
                           a1 = s1[m + 1] * rsqrtf(v1[m + 1] + EPSV) * LOG2E; }
        else if (m < 64) { r0 = w2 + (m - 32) * 256; r1 = r0 + 256;
                           a0 = s2[m - 32] * rsqrtf(v2[m - 32] + EPSV);
                           a1 = s2[m - 31] * rsqrtf(v2[m - 31] + EPSV); }
        else             { r0 = w3 + (m - 64) * 256; r1 = r0 + 256;
                           a0 = s3[m - 64] * rsqrtf(v3[m - 64] + EPSV);
                           a1 = s3[m - 63] * rsqrtf(v3[m - 63] + EPSV); }
        float4 va = *(const float4*)(r0 + kc * 4);
        float4 vb = *(const float4*)(r1 + kc * 4);
        int k0 = kc * 4;
        g_wpb[(k0 + 0) * 96 + mw] = packbf(va.x * a0, vb.x * a1);
        g_wpb[(k0 + 1) * 96 + mw] = packbf(va.y * a0, vb.y * a1);
        g_wpb[(k0 + 2) * 96 + mw] = packbf(va.z * a0, vb.z * a1);
        g_wpb[(k0 + 3) * 96 + mw] = packbf(va.w * a0, vb.w * a1);
        return;
    }
    idx -= 6144;
    if (idx < 192) {
        int r = idx;
        float bb, ss, tt, mm, vv, lg = 1.f;
        if (r < 32)      { bb = b1[r];      ss = s1[r];      tt = t1[r];      mm = m1[r];      vv = v1[r]; lg = LOG2E; }
        else if (r < 64) { bb = b2[r - 32]; ss = s2[r - 32]; tt = t2[r - 32]; mm = m2[r - 32]; vv = v2[r - 32]; }
        else             { bb = b3[r - 64]; ss = s3[r - 64]; tt = t3[r - 64]; mm = m3[r - 64]; vv = v3[r - 64]; }
        float alpha = ss * rsqrtf(vv + EPSV);
        g_abp[192 + r] = fmaf(bb - mm, alpha, tt) * lg;
    }
}

// =====================================================================
// proj+pool (R9 structure, unchanged): grid (32 p-tiles, 3 m-slices, NB)
// =====================================================================
__global__ __launch_bounds__(256) void proj_pool_kernel(const float* __restrict__ x)
{
    __shared__ __align__(16) union {
        struct { __nv_bfloat16 As[32 * 72]; __nv_bfloat16 Bs[32 * 136]; } s;
        float T[64 * 132];
    } u;
    const int b = blockIdx.z;
    const int my = blockIdx.y, m0 = my * 64;
    const int bx = blockIdx.x, p0 = bx * 128;
    const int t = threadIdx.x, lane = t & 31, w = t >> 5;
    const int g = lane >> 2, tig = lane & 3;
    const int mBase = (w >> 2) * 32, nBase = (w & 3) * 32;
    const float* xb = x + ((size_t)b << 20);
    const int ar = t >> 3, aseg = (t & 7) * 8;
    float acc[2][4][4] = {};
    uint4 wA = *(const uint4*)&g_wpb[(ar * 192 + m0 + aseg) >> 1];
    float4 va[4];
#pragma unroll
    for (int p = 0; p < 4; p++) {
        int slot = t + p * 256, r = slot >> 5, c4 = (slot & 31) * 4;
        va[p] = *(const float4*)&xb[((size_t)r << 12) + p0 + c4];
    }
    for (int kt = 0; kt < 8; kt++) {
        *(uint4*)&u.s.As[ar * 72 + aseg] = wA;
#pragma unroll
        for (int p = 0; p < 4; p++) {
            int slot = t + p * 256, r = slot >> 5, c4 = (slot & 31) * 4;
            unsigned* d = (unsigned*)&u.s.Bs[r * 136 + c4];
            d[0] = packbf(va[p].x, va[p].y);
            d[1] = packbf(va[p].z, va[p].w);
        }
        __syncthreads();
        if (kt < 7) {
            const int k0 = (kt + 1) * 32;
            wA = *(const uint4*)&g_wpb[(((kt + 1) * 32 + ar) * 192 + m0 + aseg) >> 1];
#pragma unroll
            for (int p = 0; p < 4; p++) {
                int slot = t + p * 256, r = slot >> 5, c4 = (slot & 31) * 4;
                va[p] = *(const float4*)&xb[((size_t)(k0 + r) << 12) + p0 + c4];
            }
        }
        mma_ktile<2, 4, 72, 136>(u.s.As, u.s.Bs, mBase, nBase, lane, acc);
        __syncthreads();
    }
#pragma unroll
    for (int i = 0; i < 2; i++) {
#pragma unroll
        for (int half = 0; half < 2; half++) {
            int rl = mBase + i * 16 + g + half * 8;
            float beta = g_abp[192 + m0 + rl];
#pragma unroll
            for (int j = 0; j < 4; j++) {
                int col = nBase + j * 8 + 2 * tig;
                u.T[rl * 132 + col]     = fmaxf(acc[i][j][half * 2 + 0] + beta, 0.f);
                u.T[rl * 132 + col + 1] = fmaxf(acc[i][j][half * 2 + 1] + beta, 0.f);
            }
        }
    }
    __syncthreads();
    if (my == 0) {
        {
            int k = t >> 3, nq = (t & 7) * 4;
            const float* r0 = &u.T[k * 132 + 2 * nq];
            unsigned w0 = packbf(fmaxf(fmaxf(r0[0], r0[1]), fmaxf(r0[64], r0[65])),
                                 fmaxf(fmaxf(r0[2], r0[3]), fmaxf(r0[66], r0[67])));
            unsigned w1_ = packbf(fmaxf(fmaxf(r0[4], r0[5]), fmaxf(r0[68], r0[69])),
                                  fmaxf(fmaxf(r0[6], r0[7]), fmaxf(r0[70], r0[71])));
            *(uint2*)&g_fb[((b * 32 + k) * 1024 + bx * 32 + nq) >> 1] = make_uint2(w0, w1_);
        }
        {
            int k = t >> 3, mq = (t & 7) * 16;
            const float* r0 = &u.T[(32 + k) * 132 + mq];
            uint4 o0, o1;
            o0.x = packbf(r0[0],  r0[1]);  o0.y = packbf(r0[2],  r0[3]);
            o0.z = packbf(r0[4],  r0[5]);  o0.w = packbf(r0[6],  r0[7]);
            o1.x = packbf(r0[8],  r0[9]);  o1.y = packbf(r0[10], r0[11]);
            o1.z = packbf(r0[12], r0[13]); o1.w = packbf(r0[14], r0[15]);
            unsigned base = ((b * 32 + k) * 4096 + p0 + mq) >> 1;
            *(uint4*)&g_gb[base] = o0;
            *(uint4*)&g_gb[base + 4] = o1;
        }
    } else {
        const int cg0 = (my - 1) * 64;
        int n = t & 31, cq = (t >> 5) * 8;
        unsigned pk[4];
#pragma unroll
        for (int cc = 0; cc < 4; cc++) {
            const float* ra = &u.T[(cq + 2 * cc) * 132 + 2 * n];
            const float* rb = &u.T[(cq + 2 * cc + 1) * 132 + 2 * n];
            float v0 = fmaxf(fmaxf(ra[0], ra[1]), fmaxf(ra[64], ra[65]));
            float v1_ = fmaxf(fmaxf(rb[0], rb[1]), fmaxf(rb[64], rb[65]));
            pk[cc] = packbf(v0, v1_);
        }
        *(uint4*)&g_hh2[((b * 1024 + bx * 32 + n) * 128 + cg0 + cq) >> 1] =
            make_uint4(pk[0], pk[1], pk[2], pk[3]);
    }
}

// =====================================================================
// w4 staging: fp32 w4 [m=256][k=128] -> Wst[k 32][m 128+8] bf16, alpha folded
// =====================================================================
__device__ __forceinline__ void stage_w4(__nv_bfloat16* dst, const float* __restrict__ w4,
                                         const float* a4f, int nkt, int noh, int t)
{
    int tm2 = (t & 63) * 2, tk = (t >> 6) * 8;
    int mg = noh * 128 + tm2;
    const float* r0 = w4 + mg * 128 + nkt * 32 + tk;
    const float* r1 = r0 + 128;
    float4 a = *(const float4*)r0, b_ = *(const float4*)(r0 + 4);
    float4 c = *(const float4*)r1, d = *(const float4*)(r1 + 4);
    float a0 = a4f[mg], a1 = a4f[mg + 1];
    *(unsigned*)&dst[(tk + 0) * 136 + tm2] = packbf(a.x * a0,  c.x * a1);
    *(unsigned*)&dst[(tk + 1) * 136 + tm2] = packbf(a.y * a0,  c.y * a1);
    *(unsigned*)&dst[(tk + 2) * 136 + tm2] = packbf(a.z * a0,  c.z * a1);
    *(unsigned*)&dst[(tk + 3) * 136 + tm2] = packbf(a.w * a0,  c.w * a1);
    *(unsigned*)&dst[(tk + 4) * 136 + tm2] = packbf(b_.x * a0, d.x * a1);
    *(unsigned*)&dst[(tk + 5) * 136 + tm2] = packbf(b_.y * a0, d.y * a1);
    *(unsigned*)&dst[(tk + 6) * 136 + tm2] = packbf(b_.z * a0, d.z * a1);
    *(unsigned*)&dst[(tk + 7) * 136 + tm2] = packbf(b_.w * a0, d.w * a1);
}

// =====================================================================
// fused attention + final conv, BM(m)=64/CTA, grid (64, NB).
// Mainloop: prefetch distance 2, ring-4 F/H, P 2-deep, ONE sync per iter.
// smem: Bsg@0(4608) | F@4608(4x4608) | H@23040(4x17408) | P@92672(2x9216)
//       | rowsum@111104(256)  -> total 111360
// epilogue overlay: Po@0(18432) | Wst@23040(2x8704) | a4f@45056 | b4f@46080
// =====================================================================
__global__ __launch_bounds__(256, 2) void fused_attn_kernel(
    const float* __restrict__ x, float* __restrict__ out,
    const float* __restrict__ w4,
    const float* __restrict__ b4, const float* __restrict__ s4,
    const float* __restrict__ t4, const float* __restrict__ m4,
    const float* __restrict__ v4, const float* __restrict__ gamma)
{
    extern __shared__ __align__(16) char dsm[];
    __nv_bfloat16* Bsg = (__nv_bfloat16*)dsm;                 // 32x72
    __nv_bfloat16* F   = (__nv_bfloat16*)(dsm + 4608);        // 4 x 32x72   (stride 2304 hw)
    __nv_bfloat16* H   = (__nv_bfloat16*)(dsm + 23040);       // 4 x 64x136  (stride 8704 hw)
    __nv_bfloat16* P   = (__nv_bfloat16*)(dsm + 92672);       // 2 x 64x72   (stride 4608 hw)
    float* rowsum      = (float*)(dsm + 111104);              // 64
    __nv_bfloat16* Po  = (__nv_bfloat16*)dsm;                 // 128x72 (epilogue)
    __nv_bfloat16* Wst = (__nv_bfloat16*)(dsm + 23040);       // 2 x 32x136 (epilogue)
    float* a4f         = (float*)(dsm + 45056);               // 256
    float* b4f         = (float*)(dsm + 46080);               // 256
    const int b = blockIdx.y, m0 = blockIdx.x * 64;
    const int t = threadIdx.x, lane = t & 31, w = t >> 5;
    const int g = lane >> 2, tig = lane & 3;
    const int mBaseS = (w >> 2) * 32, nBaseS = (w & 3) * 16;
    const int mBaseO = (w >> 2) * 64, nBaseO = (w & 3) * 16;
    if (t < 64) rowsum[t] = 0.f;

    const __nv_bfloat16* fb  = (const __nv_bfloat16*)g_fb  + (size_t)b * 32 * 1024;
    const __nv_bfloat16* gbp = (const __nv_bfloat16*)g_gb  + (size_t)b * 32 * 4096;
    const __nv_bfloat16* hhb = (const __nv_bfloat16*)g_hh2 + (size_t)b * 1024 * 128;
    const int fr = t >> 3, fseg = (t & 7) * 8;

    // prologue: group A = {Bsg, F[0], H[0]}, group B = {F[1], H[1]}
    cpa16(&Bsg[fr * 72 + fseg], &gbp[fr * 4096 + m0 + fseg]);
    cpa16(&F[fr * 72 + fseg], &fb[fr * 1024 + fseg]);
#pragma unroll
    for (int p = 0; p < 4; p++) {
        int slot = t + p * 256, hr = slot >> 4, hseg = (slot & 15) * 8;
        cpa16(&H[hr * 136 + hseg], &hhb[hr * 128 + hseg]);
    }
    cp_commit();
    cpa16(&F[2304 + fr * 72 + fseg], &fb[fr * 1024 + 64 + fseg]);
#pragma unroll
    for (int p = 0; p < 4; p++) {
        int slot = t + p * 256, hr = slot >> 4, hseg = (slot & 15) * 8;
        cpa16(&H[8704 + hr * 136 + hseg], &hhb[(size_t)(64 + hr) * 128 + hseg]);
    }
    cp_commit();
    cp_wait<1>();                              // slot 0 ready; slot 1 in flight
    __syncthreads();

    float acc_s[2][2][4] = {};
    float acc_o[4][2][4] = {};
    float esum[2][2] = {};

    for (int nt = 0; nt < 16; nt++) {
        // GEMM1(nt): reads F[nt&3] (guaranteed by wait<1> at end of nt-1)
        mma_ktile<2, 2, 72, 72>(F + (nt & 3) * 2304, Bsg, mBaseS, nBaseS, lane, acc_s);
        // exp -> P[nt&1]
        {
            __nv_bfloat16* Pc = P + (nt & 1) * 4608;
#pragma unroll
            for (int i = 0; i < 2; i++) {
                int row = mBaseS + i * 16 + g;
#pragma unroll
                for (int j = 0; j < 2; j++) {
                    int col = nBaseS + j * 8 + 2 * tig;
                    float e0 = ex2f(acc_s[i][j][0]);
                    float e1 = ex2f(acc_s[i][j][1]);
                    float e2 = ex2f(acc_s[i][j][2]);
                    float e3 = ex2f(acc_s[i][j][3]);
                    esum[j][0] += e0 + e2;
                    esum[j][1] += e1 + e3;
                    *(unsigned*)&Pc[row * 72 + col]       = packbf(e0, e1);
                    *(unsigned*)&Pc[(row + 8) * 72 + col] = packbf(e2, e3);
                    acc_s[i][j][0] = 0.f; acc_s[i][j][1] = 0.f;
                    acc_s[i][j][2] = 0.f; acc_s[i][j][3] = 0.f;
                }
            }
        }
        // stage nt+2 into slot (nt+2)&3 (disjoint from slots nt, nt-1, nt+1)
        if (nt < 14) {
            int s2 = (nt + 2) & 3;
            cpa16(&F[s2 * 2304 + fr * 72 + fseg], &fb[fr * 1024 + (nt + 2) * 64 + fseg]);
#pragma unroll
            for (int p = 0; p < 4; p++) {
                int slot = t + p * 256, hr = slot >> 4, hseg = (slot & 15) * 8;
                cpa16(&H[s2 * 8704 + hr * 136 + hseg],
                      &hhb[(size_t)((nt + 2) * 64 + hr) * 128 + hseg]);
            }
            cp_commit();
        }
        // GEMM2(nt-1): H[(nt-1)&3], P[(nt-1)&1]
        if (nt > 0) {
            const __nv_bfloat16* Hp = H + ((nt - 1) & 3) * 8704;
            const __nv_bfloat16* Pp = P + ((nt - 1) & 1) * 4608;
            mma_ktile<4, 2, 136, 72>(Hp,            Pp,           mBaseO, nBaseO, lane, acc_o);
            mma_ktile<4, 2, 136, 72>(Hp + 32 * 136, Pp + 32 * 72, mBaseO, nBaseO, lane, acc_o);
        }
        if (nt < 14) cp_wait<1>(); else cp_wait<0>();
        __syncthreads();                       // cp arrival (slot nt+1) + P publication
    }
    // tail: GEMM2(15): H[3], P[1]
    {
        const __nv_bfloat16* Hp = H + 3 * 8704;
        const __nv_bfloat16* Pp = P + 4608;
        mma_ktile<4, 2, 136, 72>(Hp,            Pp,           mBaseO, nBaseO, lane, acc_o);
        mma_ktile<4, 2, 136, 72>(Hp + 32 * 136, Pp + 32 * 72, mBaseO, nBaseO, lane, acc_o);
    }
#pragma unroll
    for (int j = 0; j < 2; j++) {
        int col = nBaseO + j * 8 + 2 * tig;
        atomicAdd(&rowsum[col],     esum[j][0]);
        atomicAdd(&rowsum[col + 1], esum[j][1]);
    }
    // BN4 fold (gamma included) -> a4f/b4f
    {
        float gm = gamma[0];
        float al = s4[t] * rsqrtf(v4[t] + EPSV);
        a4f[t] = al * gm;
        b4f[t] = fmaf(b4[t] - m4[t], al, t4[t]) * gm;
    }
    __syncthreads();                           // rowsum + a4f/b4f visible; mainloop smem dead
    // normalize o -> Po[c 128][m 64+8] bf16
#pragma unroll
    for (int j = 0; j < 2; j++) {
        int col = nBaseO + j * 8 + 2 * tig;
        float inv0 = 1.f / rowsum[col], inv1 = 1.f / rowsum[col + 1];
#pragma unroll
        for (int i = 0; i < 4; i++) {
            int c = mBaseO + i * 16 + g;
            *(unsigned*)&Po[c * 72 + col] =
                packbf(acc_o[i][j][0] * inv0, acc_o[i][j][1] * inv1);
            *(unsigned*)&Po[(c + 8) * 72 + col] =
                packbf(acc_o[i][j][2] * inv0, acc_o[i][j][3] * inv1);
        }
    }
    // stage w4 tile for step 0
    stage_w4(Wst, w4, a4f, 0, 0, t);
    cp_commit();

    for (int oh = 0; oh < 2; oh++) {
        float acc_f[4][2][4] = {};
#pragma unroll
        for (int kt = 0; kt < 4; kt++) {
            int s = oh * 4 + kt;
            cp_wait<0>();
            __syncthreads();                   // Wst[s&1] + Po visible
            if (s < 7) {
                int ns = s + 1;
                stage_w4(Wst + (ns & 1) * 4352, w4, a4f, ns & 3, ns >> 2, t);
                cp_commit();
            }
            mma_ktile<4, 2, 136, 72>(Wst + (s & 1) * 4352, Po + kt * 32 * 72,
                                     mBaseO, nBaseO, lane, acc_f);
        }
#pragma unroll
        for (int i = 0; i < 4; i++) {
#pragma unroll
            for (int half = 0; half < 2; half++) {
                int r = oh * 128 + mBaseO + i * 16 + g + half * 8;
                float gb = b4f[r];
                size_t base = ((size_t)(b * 256 + r) << 12) + m0;
#pragma unroll
                for (int j = 0; j < 2; j++) {
                    int col = nBaseO + j * 8 + 2 * tig;
                    float2 xv = *(const float2*)&x[base + col];
                    float2 o;
                    o.x = acc_f[i][j][half * 2 + 0] + gb + xv.x;
                    o.y = acc_f[i][j][half * 2 + 1] + gb + xv.y;
                    *(float2*)&out[base + col] = o;
                }
            }
        }
    }
}

// =====================================================================
extern "C" void kernel_launch(void* const* d_in, const int* in_sizes, int n_in,
                              void* d_out, int out_size)
{
    const float* x  = (const float*)d_in[0];
    const float* w1 = (const float*)d_in[1],  *b1 = (const float*)d_in[2],
               * s1 = (const float*)d_in[3],  *t1 = (const float*)d_in[4],
               * m1 = (const float*)d_in[5],  *v1 = (const float*)d_in[6];
    const float* w2 = (const float*)d_in[7],  *b2 = (const float*)d_in[8],
               * s2 = (const float*)d_in[9],  *t2 = (const float*)d_in[10],
               * m2 = (const float*)d_in[11], *v2 = (const float*)d_in[12];
    const float* w3 = (const float*)d_in[13], *b3 = (const float*)d_in[14],
               * s3 = (const float*)d_in[15], *t3 = (const float*)d_in[16],
               * m3 = (const float*)d_in[17], *v3 = (const float*)d_in[18];
    const float* w4 = (const float*)d_in[19], *b4 = (const float*)d_in[20],
               * s4 = (const float*)d_in[21], *t4 = (const float*)d_in[22],
               * m4 = (const float*)d_in[23], *v4 = (const float*)d_in[24];
    const float* gamma = (const float*)d_in[25];
    float* out = (float*)d_out;

    cudaFuncSetAttribute(fused_attn_kernel,
                         cudaFuncAttributeMaxDynamicSharedMemorySize, 111616);

    pre_kernel<<<25, 256>>>(w1, w2, w3,
                            b1, s1, t1, m1, v1,
                            b2, s2, t2, m2, v2,
                            b3, s3, t3, m3, v3);

    proj_pool_kernel<<<dim3(32, 3, NB), 256>>>(x);

    fused_attn_kernel<<<dim3(64, NB), 256, 111360>>>(x, out, w4, b4, s4, t4, m4, v4, gamma);
}

// round 15
// speedup vs baseline: 1.1946x; 1.1946x over previous
#include <cuda_runtime.h>
#include <cuda_bf16.h>
#include <math.h>

#define NB 8
#define NC 256
#define HWF 4096
#define HW4 1024
#define EPSV 1e-5f
#define LOG2E 1.4426950408889634f

// ---------------- scratch (static __device__, word-typed, no allocation) ----
__device__ unsigned g_wpb [24576];               // proj wT bf16 [k=256][m=192], alpha-folded (m-pairs/word)
__device__ unsigned g_w4b [16384];               // w4T bf16 [k=128][m=256], gamma*alpha4 folded
__device__ float    g_abp[2 * 192];              // proj beta
__device__ float    g_ab4[2 * 256];              // final gamma*beta4 in [256..]
__device__ unsigned g_fb [NB * 32 * 512];        // f bf16 [b][k=32][n=1024]  (log2e folded)
__device__ unsigned g_gb [NB * 32 * 2048];       // g bf16 [b][k=32][m=4096]
__device__ unsigned g_hh2[NB * 1024 * 64];       // hh bf16 [b][n=1024][c=128]
__device__ unsigned g_ob [NB * 128 * 2048];      // (unused, kept for layout stability)

// ---------------- helpers ----------------
__device__ __forceinline__ unsigned packbf(float a, float b) {
    __nv_bfloat162 t = __floats2bfloat162_rn(a, b);
    return *(unsigned*)&t;
}
__device__ __forceinline__ float ex2f(float f) {
    float r; asm("ex2.approx.ftz.f32 %0, %1;" : "=f"(r) : "f"(f)); return r;
}
__device__ __forceinline__ void cpa16(void* s, const void* g) {
    unsigned a = (unsigned)__cvta_generic_to_shared(s);
    asm volatile("cp.async.ca.shared.global [%0], [%1], 16;" :: "r"(a), "l"(g));
}
__device__ __forceinline__ void cp_commit() { asm volatile("cp.async.commit_group;"); }
template<int N> __device__ __forceinline__ void cp_wait() {
    asm volatile("cp.async.wait_group %0;" :: "n"(N));
}
__device__ __forceinline__ void ldsm4t(unsigned* r, const __nv_bfloat16* p) {
    unsigned a = (unsigned)__cvta_generic_to_shared(p);
    asm volatile("ldmatrix.sync.aligned.m8n8.x4.trans.shared.b16 {%0,%1,%2,%3}, [%4];"
                 : "=r"(r[0]), "=r"(r[1]), "=r"(r[2]), "=r"(r[3]) : "r"(a));
}
__device__ __forceinline__ void mma16(float* d, const unsigned* a, const unsigned* b) {
    asm volatile(
        "mma.sync.aligned.m16n8k16.row.col.f32.bf16.bf16.f32 "
        "{%0,%1,%2,%3},{%4,%5,%6,%7},{%8,%9},{%0,%1,%2,%3};"
        : "+f"(d[0]), "+f"(d[1]), "+f"(d[2]), "+f"(d[3])
        : "r"(a[0]), "r"(a[1]), "r"(a[2]), "r"(a[3]), "r"(b[0]), "r"(b[1]));
}

// A-frag (m16k16) from [k][row] smem, stride S halfwords, via ldmatrix.x4.trans
template<int S>
__device__ __forceinline__ void lda(unsigned* a, const __nv_bfloat16* base,
                                    int mo, int k0, int lane) {
    int grp = lane >> 3, j = lane & 7;
    int row = k0 + ((grp & 2) << 2) + j;
    int col = mo + ((grp & 1) << 3);
    ldsm4t(a, base + row * S + col);
}
// two B-frags (n8k16 at no, no+8) in one x4.trans
template<int S>
__device__ __forceinline__ void ldb2(unsigned* b, const __nv_bfloat16* base,
                                     int no, int k0, int lane) {
    int grp = lane >> 3, j = lane & 7;
    int row = k0 + ((grp & 1) << 3) + j;
    int col = no + ((grp >> 1) << 3);
    ldsm4t(b, base + row * S + col);
}

// one 32-deep k tile. As[k][m] stride AS, Bs[k][n] stride BS (halfwords).
template<int MF, int NF, int AS, int BS>
__device__ __forceinline__ void mma_ktile(const __nv_bfloat16* As, const __nv_bfloat16* Bs,
                                          int mBase, int nBase, int lane,
                                          float (*acc)[NF][4])
{
#pragma unroll
    for (int ks = 0; ks < 2; ks++) {
        unsigned a[MF][4], b[NF][2];
#pragma unroll
        for (int i = 0; i < MF; i++) lda<AS>(a[i], As, mBase + i * 16, ks * 16, lane);
#pragma unroll
        for (int j = 0; j < NF; j += 2) {
            unsigned bb[4];
            ldb2<BS>(bb, Bs, nBase + j * 8, ks * 16, lane);
            b[j][0] = bb[0]; b[j][1] = bb[1];
            b[j + 1][0] = bb[2]; b[j + 1][1] = bb[3];
        }
#pragma unroll
        for (int i = 0; i < MF; i++)
#pragma unroll
            for (int j = 0; j < NF; j++)
                mma16(acc[i][j], a[i], b[j]);
    }
}

// =====================================================================
// pre: coalesced reads (each 256-thread group sweeps one weight row pair)
// =====================================================================
__global__ void pre_kernel(const float* __restrict__ w1, const float* __restrict__ w2,
                           const float* __restrict__ w3, const float* __restrict__ w4,
                           const float* __restrict__ b1, const float* __restrict__ s1,
                           const float* __restrict__ t1, const float* __restrict__ m1,
                           const float* __restrict__ v1,
                           const float* __restrict__ b2, const float* __restrict__ s2,
                           const float* __restrict__ t2, const float* __restrict__ m2,
                           const float* __restrict__ v2,
                           const float* __restrict__ b3, const float* __restrict__ s3,
                           const float* __restrict__ t3, const float* __restrict__ m3,
                           const float* __restrict__ v3,
                           const float* __restrict__ b4, const float* __restrict__ s4,
                           const float* __restrict__ t4, const float* __restrict__ m4,
                           const float* __restrict__ v4,
                           const float* __restrict__ gamma)
{
    int idx = blockIdx.x * 256 + threadIdx.x;
    if (idx < 24576) {                       // wpb: mw-major, k-minor -> coalesced weight reads
        int mw = idx >> 8, k = idx & 255;
        int m = 2 * mw;
        float a0, a1, v0, v1_;
        if (m < 32)      { a0 = s1[m] * rsqrtf(v1[m] + EPSV) * LOG2E;
                           a1 = s1[m + 1] * rsqrtf(v1[m + 1] + EPSV) * LOG2E;
                           v0 = w1[m * 256 + k]; v1_ = w1[(m + 1) * 256 + k]; }
        else if (m < 64) { a0 = s2[m - 32] * rsqrtf(v2[m - 32] + EPSV);
                           a1 = s2[m - 31] * rsqrtf(v2[m - 31] + EPSV);
                           v0 = w2[(m - 32) * 256 + k]; v1_ = w2[(m - 31) * 256 + k]; }
        else             { a0 = s3[m - 64] * rsqrtf(v3[m - 64] + EPSV);
                           a1 = s3[m - 63] * rsqrtf(v3[m - 63] + EPSV);
                           v0 = w3[(m - 64) * 256 + k]; v1_ = w3[(m - 63) * 256 + k]; }
        g_wpb[k * 96 + mw] = packbf(v0 * a0, v1_ * a1);
        return;
    }
    idx -= 24576;
    if (idx < 16384) {                       // w4b: mw-major, k-minor -> coalesced reads
        int mw = idx >> 7, k = idx & 127;
        int m = 2 * mw;
        float a0 = s4[m] * rsqrtf(v4[m] + EPSV) * gamma[0];
        float a1 = s4[m + 1] * rsqrtf(v4[m + 1] + EPSV) * gamma[0];
        g_w4b[k * 128 + mw] = packbf(w4[m * 128 + k] * a0, w4[(m + 1) * 128 + k] * a1);
        return;
    }
    idx -= 16384;
    if (idx < 192) {
        int r = idx;
        float bb, ss, tt, mm, vv, lg = 1.f;
        if (r < 32)      { bb = b1[r];      ss = s1[r];      tt = t1[r];      mm = m1[r];      vv = v1[r]; lg = LOG2E; }
        else if (r < 64) { bb = b2[r - 32]; ss = s2[r - 32]; tt = t2[r - 32]; mm = m2[r - 32]; vv = v2[r - 32]; }
        else             { bb = b3[r - 64]; ss = s3[r - 64]; tt = t3[r - 64]; mm = m3[r - 64]; vv = v3[r - 64]; }
        float alpha = ss * rsqrtf(vv + EPSV);
        g_abp[192 + r] = fmaf(bb - mm, alpha, tt) * lg;
        return;
    }
    idx -= 192;
    if (idx < 256) {
        int r = idx;
        float alpha = s4[r] * rsqrtf(v4[r] + EPSV);
        g_ab4[256 + r] = fmaf(b4[r] - m4[r], alpha, t4[r]) * gamma[0];
    }
}

// =====================================================================
// proj+pool (R9 structure): grid (32 p-tiles, 3 m-slices, NB)
// =====================================================================
__global__ __launch_bounds__(256) void proj_pool_kernel(const float* __restrict__ x)
{
    __shared__ __align__(16) union {
        struct { __nv_bfloat16 As[32 * 72]; __nv_bfloat16 Bs[32 * 136]; } s;
        float T[64 * 132];
    } u;
    const int b = blockIdx.z;
    const int my = blockIdx.y, m0 = my * 64;
    const int bx = blockIdx.x, p0 = bx * 128;
    const int t = threadIdx.x, lane = t & 31, w = t >> 5;
    const int g = lane >> 2, tig = lane & 3;
    const int mBase = (w >> 2) * 32, nBase = (w & 3) * 32;
    const float* xb = x + ((size_t)b << 20);
    const int ar = t >> 3, aseg = (t & 7) * 8;
    float acc[2][4][4] = {};
    uint4 wA = *(const uint4*)&g_wpb[(ar * 192 + m0 + aseg) >> 1];
    float4 va[4];
#pragma unroll
    for (int p = 0; p < 4; p++) {
        int slot = t + p * 256, r = slot >> 5, c4 = (slot & 31) * 4;
        va[p] = *(const float4*)&xb[((size_t)r << 12) + p0 + c4];
    }
    for (int kt = 0; kt < 8; kt++) {
        *(uint4*)&u.s.As[ar * 72 + aseg] = wA;
#pragma unroll
        for (int p = 0; p < 4; p++) {
            int slot = t + p * 256, r = slot >> 5, c4 = (slot & 31) * 4;
            unsigned* d = (unsigned*)&u.s.Bs[r * 136 + c4];
            d[0] = packbf(va[p].x, va[p].y);
            d[1] = packbf(va[p].z, va[p].w);
        }
        __syncthreads();
        if (kt < 7) {
            const int k0 = (kt + 1) * 32;
            wA = *(const uint4*)&g_wpb[(((kt + 1) * 32 + ar) * 192 + m0 + aseg) >> 1];
#pragma unroll
            for (int p = 0; p < 4; p++) {
                int slot = t + p * 256, r = slot >> 5, c4 = (slot & 31) * 4;
                va[p] = *(const float4*)&xb[((size_t)(k0 + r) << 12) + p0 + c4];
            }
        }
        mma_ktile<2, 4, 72, 136>(u.s.As, u.s.Bs, mBase, nBase, lane, acc);
        __syncthreads();
    }
#pragma unroll
    for (int i = 0; i < 2; i++) {
#pragma unroll
        for (int half = 0; half < 2; half++) {
            int rl = mBase + i * 16 + g + half * 8;
            float beta = g_abp[192 + m0 + rl];
#pragma unroll
            for (int j = 0; j < 4; j++) {
                int col = nBase + j * 8 + 2 * tig;
                u.T[rl * 132 + col]     = fmaxf(acc[i][j][half * 2 + 0] + beta, 0.f);
                u.T[rl * 132 + col + 1] = fmaxf(acc[i][j][half * 2 + 1] + beta, 0.f);
            }
        }
    }
    __syncthreads();
    if (my == 0) {
        {
            int k = t >> 3, nq = (t & 7) * 4;
            const float* r0 = &u.T[k * 132 + 2 * nq];
            unsigned w0 = packbf(fmaxf(fmaxf(r0[0], r0[1]), fmaxf(r0[64], r0[65])),
                                 fmaxf(fmaxf(r0[2], r0[3]), fmaxf(r0[66], r0[67])));
            unsigned w1_ = packbf(fmaxf(fmaxf(r0[4], r0[5]), fmaxf(r0[68], r0[69])),
                                  fmaxf(fmaxf(r0[6], r0[7]), fmaxf(r0[70], r0[71])));
            *(uint2*)&g_fb[((b * 32 + k) * 1024 + bx * 32 + nq) >> 1] = make_uint2(w0, w1_);
        }
        {
            int k = t >> 3, mq = (t & 7) * 16;
            const float* r0 = &u.T[(32 + k) * 132 + mq];
            uint4 o0, o1;
            o0.x = packbf(r0[0],  r0[1]);  o0.y = packbf(r0[2],  r0[3]);
            o0.z = packbf(r0[4],  r0[5]);  o0.w = packbf(r0[6],  r0[7]);
            o1.x = packbf(r0[8],  r0[9]);  o1.y = packbf(r0[10], r0[11]);
            o1.z = packbf(r0[12], r0[13]); o1.w = packbf(r0[14], r0[15]);
            unsigned base = ((b * 32 + k) * 4096 + p0 + mq) >> 1;
            *(uint4*)&g_gb[base] = o0;
            *(uint4*)&g_gb[base + 4] = o1;
        }
    } else {
        const int cg0 = (my - 1) * 64;
        int n = t & 31, cq = (t >> 5) * 8;
        unsigned pk[4];
#pragma unroll
        for (int cc = 0; cc < 4; cc++) {
            const float* ra = &u.T[(cq + 2 * cc) * 132 + 2 * n];
            const float* rb = &u.T[(cq + 2 * cc + 1) * 132 + 2 * n];
            float v0 = fmaxf(fmaxf(ra[0], ra[1]), fmaxf(ra[64], ra[65]));
            float v1_ = fmaxf(fmaxf(rb[0], rb[1]), fmaxf(rb[64], rb[65]));
            pk[cc] = packbf(v0, v1_);
        }
        *(uint4*)&g_hh2[((b * 1024 + bx * 32 + n) * 128 + cg0 + cq) >> 1] =
            make_uint4(pk[0], pk[1], pk[2], pk[3]);
    }
}

// =====================================================================
// fused attention + final conv (R9 exact), BM(m)=64/CTA, grid (64, NB).
// smem: Bsg[32x72] | F[2][32x72] | H[2][64x136] | P[32x... 64x72] | rowsum
// epilogue overlay: Po[128x72] at 0 | Wst[2][32x136] at 20480
// =====================================================================
__global__ __launch_bounds__(256, 2) void fused_attn_kernel(const float* __restrict__ x,
                                                            float* __restrict__ out)
{
    extern __shared__ __align__(16) char dsm[];
    __nv_bfloat16* Bsg = (__nv_bfloat16*)dsm;                 // 32x72
    __nv_bfloat16* F   = (__nv_bfloat16*)(dsm + 4608);        // 2 x 32x72
    __nv_bfloat16* H   = (__nv_bfloat16*)(dsm + 13824);       // 2 x 64x136
    __nv_bfloat16* P   = (__nv_bfloat16*)(dsm + 48640);       // 64x72
    float* rowsum      = (float*)(dsm + 57856);               // 64
    __nv_bfloat16* Po  = (__nv_bfloat16*)dsm;                 // 128x72 (epilogue)
    __nv_bfloat16* Wst = (__nv_bfloat16*)(dsm + 20480);       // 2 x 32x136 (epilogue)
    const int b = blockIdx.y, m0 = blockIdx.x * 64;
    const int t = threadIdx.x, lane = t & 31, w = t >> 5;
    const int g = lane >> 2, tig = lane & 3;
    const int mBaseS = (w >> 2) * 32, nBaseS = (w & 3) * 16;
    const int mBaseO = (w >> 2) * 64, nBaseO = (w & 3) * 16;
    if (t < 64) rowsum[t] = 0.f;

    const __nv_bfloat16* fb  = (const __nv_bfloat16*)g_fb  + (size_t)b * 32 * 1024;
    const __nv_bfloat16* gbp = (const __nv_bfloat16*)g_gb  + (size_t)b * 32 * 4096;
    const __nv_bfloat16* hhb = (const __nv_bfloat16*)g_hh2 + (size_t)b * 1024 * 128;
    const __nv_bfloat16* w4b = (const __nv_bfloat16*)g_w4b;
    const int fr = t >> 3, fseg = (t & 7) * 8;

    // prologue: Bsg + stage 0
    cpa16(&Bsg[fr * 72 + fseg], &gbp[fr * 4096 + m0 + fseg]);
    cpa16(&F[fr * 72 + fseg], &fb[fr * 1024 + fseg]);
#pragma unroll
    for (int p = 0; p < 4; p++) {
        int slot = t + p * 256, hr = slot >> 4, hseg = (slot & 15) * 8;
        cpa16(&H[hr * 136 + hseg], &hhb[hr * 128 + hseg]);
    }
    cp_commit();

    float acc_s[2][2][4] = {};
    float acc_o[4][2][4] = {};
    float esum[2][2] = {};

    for (int nt = 0; nt < 16; nt++) {
        cp_wait<0>();
        __syncthreads();                         // F/H[cur] ready; GEMM2(nt-1) done
        if (nt < 15) {
            const int bn = (nt + 1) & 1;
            cpa16(&F[bn * 2304 + fr * 72 + fseg], &fb[fr * 1024 + (nt + 1) * 64 + fseg]);
#pragma unroll
            for (int p = 0; p < 4; p++) {
                int slot = t + p * 256, hr = slot >> 4, hseg = (slot & 15) * 8;
                cpa16(&H[bn * 8704 + hr * 136 + hseg],
                      &hhb[(size_t)((nt + 1) * 64 + hr) * 128 + hseg]);
            }
            cp_commit();
        }
        const __nv_bfloat16* Fc = F + (nt & 1) * 2304;
        const __nv_bfloat16* Hc = H + (nt & 1) * 8704;
        mma_ktile<2, 2, 72, 72>(Fc, Bsg, mBaseS, nBaseS, lane, acc_s);
#pragma unroll
        for (int i = 0; i < 2; i++) {
            int row = mBaseS + i * 16 + g;
#pragma unroll
            for (int j = 0; j < 2; j++) {
                int col = nBaseS + j * 8 + 2 * tig;
                float e0 = ex2f(acc_s[i][j][0]);
                float e1 = ex2f(acc_s[i][j][1]);
                float e2 = ex2f(acc_s[i][j][2]);
                float e3 = ex2f(acc_s[i][j][3]);
                esum[j][0] += e0 + e2;
                esum[j][1] += e1 + e3;
                *(unsigned*)&P[row * 72 + col]       = packbf(e0, e1);
                *(unsigned*)&P[(row + 8) * 72 + col] = packbf(e2, e3);
                acc_s[i][j][0] = 0.f; acc_s[i][j][1] = 0.f;
                acc_s[i][j][2] = 0.f; acc_s[i][j][3] = 0.f;
            }
        }
        __syncthreads();                         // P visible
        mma_ktile<4, 2, 136, 72>(Hc,            P,           mBaseO, nBaseO, lane, acc_o);
        mma_ktile<4, 2, 136, 72>(Hc + 32 * 136, P + 32 * 72, mBaseO, nBaseO, lane, acc_o);
    }
#pragma unroll
    for (int j = 0; j < 2; j++) {
        int col = nBaseO + j * 8 + 2 * tig;
        atomicAdd(&rowsum[col],     esum[j][0]);
        atomicAdd(&rowsum[col + 1], esum[j][1]);
    }
    __syncthreads();
    // normalize o -> Po[c 128][m 64+8] bf16 (overlays Bsg/F — dead)
#pragma unroll
    for (int j = 0; j < 2; j++) {
        int col = nBaseO + j * 8 + 2 * tig;
        float inv0 = 1.f / rowsum[col], inv1 = 1.f / rowsum[col + 1];
#pragma unroll
        for (int i = 0; i < 4; i++) {
            int c = mBaseO + i * 16 + g;
            *(unsigned*)&Po[c * 72 + col] =
                packbf(acc_o[i][j][0] * inv0, acc_o[i][j][1] * inv1);
            *(unsigned*)&Po[(c + 8) * 72 + col] =
                packbf(acc_o[i][j][2] * inv0, acc_o[i][j][3] * inv1);
        }
    }
    // stage w4 tile for step 0 (overlays H region — dead)
#pragma unroll
    for (int p = 0; p < 2; p++) {
        int slot = t + p * 256, r = slot >> 4, sg = (slot & 15) * 8;
        cpa16(&Wst[r * 136 + sg], &w4b[r * 256 + sg]);
    }
    cp_commit();
    __syncthreads();                           // Po visible

    for (int oh = 0; oh < 2; oh++) {
        float acc_f[4][2][4] = {};
#pragma unroll
        for (int kt = 0; kt < 4; kt++) {
            int s = oh * 4 + kt;
            cp_wait<0>();
            __syncthreads();
            if (s < 7) {
                int ns = s + 1;
                int nkt = ns & 3, noh = ns >> 2;
                const int bn = ns & 1;
#pragma unroll
                for (int p = 0; p < 2; p++) {
                    int slot = t + p * 256, r = slot >> 4, sg = (slot & 15) * 8;
                    cpa16(&Wst[bn * 4352 + r * 136 + sg],
                          &w4b[(nkt * 32 + r) * 256 + noh * 128 + sg]);
                }
                cp_commit();
            }
            mma_ktile<4, 2, 136, 72>(Wst + (s & 1) * 4352, Po + kt * 32 * 72,
                                     mBaseO, nBaseO, lane, acc_f);
        }
#pragma unroll
        for (int i = 0; i < 4; i++) {
#pragma unroll
            for (int half = 0; half < 2; half++) {
                int r = oh * 128 + mBaseO + i * 16 + g + half * 8;
                float gb = g_ab4[256 + r];
                size_t base = ((size_t)(b * 256 + r) << 12) + m0;
#pragma unroll
                for (int j = 0; j < 2; j++) {
                    int col = nBaseO + j * 8 + 2 * tig;
                    float2 xv = *(const float2*)&x[base + col];
                    float2 o;
                    o.x = acc_f[i][j][half * 2 + 0] + gb + xv.x;
                    o.y = acc_f[i][j][half * 2 + 1] + gb + xv.y;
                    *(float2*)&out[base + col] = o;
                }
            }
        }
    }
}

// =====================================================================
extern "C" void kernel_launch(void* const* d_in, const int* in_sizes, int n_in,
                              void* d_out, int out_size)
{
    const float* x  = (const float*)d_in[0];
    const float* w1 = (const float*)d_in[1],  *b1 = (const float*)d_in[2],
               * s1 = (const float*)d_in[3],  *t1 = (const float*)d_in[4],
               * m1 = (const float*)d_in[5],  *v1 = (const float*)d_in[6];
    const float* w2 = (const float*)d_in[7],  *b2 = (const float*)d_in[8],
               * s2 = (const float*)d_in[9],  *t2 = (const float*)d_in[10],
               * m2 = (const float*)d_in[11], *v2 = (const float*)d_in[12];
    const float* w3 = (const float*)d_in[13], *b3 = (const float*)d_in[14],
               * s3 = (const float*)d_in[15], *t3 = (const float*)d_in[16],
               * m3 = (const float*)d_in[17], *v3 = (const float*)d_in[18];
    const float* w4 = (const float*)d_in[19], *b4 = (const float*)d_in[20],
               * s4 = (const float*)d_in[21], *t4 = (const float*)d_in[22],
               * m4 = (const float*)d_in[23], *v4 = (const float*)d_in[24];
    const float* gamma = (const float*)d_in[25];
    float* out = (float*)d_out;

    cudaFuncSetAttribute(fused_attn_kernel,
                         cudaFuncAttributeMaxDynamicSharedMemorySize, 59392);

    pre_kernel<<<162, 256>>>(w1, w2, w3, w4,
                             b1, s1, t1, m1, v1,
                             b2, s2, t2, m2, v2,
                             b3, s3, t3, m3, v3,
                             b4, s4, t4, m4, v4, gamma);

    proj_pool_kernel<<<dim3(32, 3, NB), 256>>>(x);

    fused_attn_kernel<<<dim3(64, NB), 256, 58112>>>(x, out);
}